// round 2
// baseline (speedup 1.0000x reference)
#include <cuda_runtime.h>
#include <math.h>

#define BB 1536
#define NG 64
#define NP 24
#define ED 64
#define HD 128
#define SEQ 12

// packed f32x2 FMA (2 fp32 FMAs per issue slot; ptxas never emits this from C++)
#define FMA2(acc, a, b) asm("fma.rn.f32x2 %0, %1, %2, %0;" : "+l"(acc) : "l"(a), "l"(b))
#define PACK2(d, s)     asm("mov.b64 %0, {%1, %1};" : "=l"(d) : "f"(s))

// ---------------- scratch (static device globals; no allocation) -------------
__device__ float g_h[BB*HD];        // carry hidden (refreshed by mlp2)
__device__ float g_c[BB*HD];        // LSTM cell
__device__ float g_hl[BB*HD];       // LSTM output h for this step
__device__ float g_lp[BB*2];        // current position
__device__ float g_decin[BB*ED];    // decoder input embedding
__device__ float g_hcon[BB*512];    // h @ Wp1_h^T + combined bias (pre-relu)
__device__ float g_pool[BB*1024];   // pooled features
__device__ float g_mh[BB*1024];     // mlp hidden
__device__ float g_M[512*2];        // Wp1_e @ Wp_emb  (512x2)
__device__ float g_biasc[512];      // bp1 + Wp1_e @ bp_emb
__device__ float g_WihT[64*512];    // transposed LSTM weights
__device__ float g_WhhT[128*512];

// ---------------- precompute: transpose LSTM weights, fold pool layer-1 ------
__global__ void precompute_kernel(const float* __restrict__ Wih,
                                  const float* __restrict__ Whh,
                                  const float* __restrict__ Wp1,
                                  const float* __restrict__ Wp_emb,
                                  const float* __restrict__ bp_emb,
                                  const float* __restrict__ bp1) {
    int idx = blockIdx.x * blockDim.x + threadIdx.x;
    if (idx < 512*64)  { int r = idx/64,  c = idx%64;  g_WihT[c*512 + r] = Wih[idx]; }
    if (idx < 512*128) { int r = idx/128, c = idx%128; g_WhhT[c*512 + r] = Whh[idx]; }
    if (idx < 512) {
        float m0 = 0.f, m1 = 0.f, bc = 0.f;
        for (int e = 0; e < 64; e++) {
            float w = Wp1[idx*192 + e];
            m0 += w * Wp_emb[e*2 + 0];
            m1 += w * Wp_emb[e*2 + 1];
            bc += w * bp_emb[e];
        }
        g_M[idx*2 + 0] = m0;
        g_M[idx*2 + 1] = m1;
        g_biasc[idx] = bp1[idx] + bc;
    }
}

// ---------------- init: carry state + first decoder input --------------------
__global__ void init_kernel(const float* __restrict__ h0, const float* __restrict__ c0,
                            const float* __restrict__ lp, const float* __restrict__ lpr,
                            const float* __restrict__ Wemb, const float* __restrict__ bemb) {
    int idx = blockIdx.x * blockDim.x + threadIdx.x;
    if (idx < BB*HD) { g_h[idx] = h0[idx]; g_c[idx] = c0[idx]; }
    if (idx < BB*2)  { g_lp[idx] = lp[idx]; }
    if (idx < BB*ED) {
        int b = idx / ED, e = idx % ED;
        g_decin[idx] = lpr[b*2]*Wemb[e*2] + lpr[b*2+1]*Wemb[e*2+1] + bemb[e];
    }
}

// ---------------- fused LSTM step: gates + activations -----------------------
__global__ void lstm_kernel(const float* __restrict__ bih, const float* __restrict__ bhh) {
    int tid = threadIdx.x;
    int u = tid & 127;
    int rh = tid >> 7;
    int r0 = blockIdx.x * 8;
    __shared__ float xs[8][64];
    __shared__ float hs[8][128];
    for (int l = tid; l < 8*64;  l += 256) xs[l>>6][l&63]   = g_decin[r0*64  + l];
    for (int l = tid; l < 8*128; l += 256) hs[l>>7][l&127]  = g_h[r0*128 + l];
    __syncthreads();

    float acc[4][4];
    #pragma unroll
    for (int gt = 0; gt < 4; gt++) {
        float bb = bih[u + gt*128] + bhh[u + gt*128];
        #pragma unroll
        for (int r = 0; r < 4; r++) acc[gt][r] = bb;
    }
    for (int e = 0; e < 64; e++) {
        float w0 = g_WihT[e*512 + u];
        float w1 = g_WihT[e*512 + u + 128];
        float w2 = g_WihT[e*512 + u + 256];
        float w3 = g_WihT[e*512 + u + 384];
        #pragma unroll
        for (int r = 0; r < 4; r++) {
            float x = xs[rh*4 + r][e];
            acc[0][r] += w0*x; acc[1][r] += w1*x; acc[2][r] += w2*x; acc[3][r] += w3*x;
        }
    }
    for (int e = 0; e < 128; e++) {
        float w0 = g_WhhT[e*512 + u];
        float w1 = g_WhhT[e*512 + u + 128];
        float w2 = g_WhhT[e*512 + u + 256];
        float w3 = g_WhhT[e*512 + u + 384];
        #pragma unroll
        for (int r = 0; r < 4; r++) {
            float x = hs[rh*4 + r][e];
            acc[0][r] += w0*x; acc[1][r] += w1*x; acc[2][r] += w2*x; acc[3][r] += w3*x;
        }
    }
    #pragma unroll
    for (int r = 0; r < 4; r++) {
        int row = r0 + rh*4 + r;
        float ig = 1.f / (1.f + __expf(-acc[0][r]));
        float fg = 1.f / (1.f + __expf(-acc[1][r]));
        float gg = tanhf(acc[2][r]);
        float og = 1.f / (1.f + __expf(-acc[3][r]));
        int bi = row*128 + u;
        float cc = fg * g_c[bi] + ig * gg;
        g_c[bi]  = cc;
        g_hl[bi] = og * tanhf(cc);
    }
}

// ---------------- rel_pos, position update, rels output, next dec_in ---------
__global__ void posdec_kernel(const float* __restrict__ Wpos, const float* __restrict__ bpos,
                              const float* __restrict__ Wemb, const float* __restrict__ bemb,
                              float* __restrict__ rels_out, int step) {
    int b = blockIdx.x;
    int t = threadIdx.x;
    __shared__ float hr[128];
    __shared__ float sr[2];
    hr[t] = g_hl[b*128 + t];
    __syncthreads();
    int w = t >> 5, lane = t & 31;
    if (w < 2) {
        float part = 0.f;
        for (int k = lane; k < 128; k += 32) part += hr[k] * Wpos[w*128 + k];
        #pragma unroll
        for (int off = 16; off; off >>= 1) part += __shfl_down_sync(0xffffffffu, part, off);
        if (lane == 0) sr[w] = part + bpos[w];
    }
    __syncthreads();
    float ra = sr[0], rb = sr[1];
    if (t < 64) g_decin[b*64 + t] = ra*Wemb[t*2] + rb*Wemb[t*2+1] + bemb[t];
    if (t == 0) {
        rels_out[(step*BB + b)*2 + 0] = ra;
        rels_out[(step*BB + b)*2 + 1] = rb;
        g_lp[b*2 + 0] += ra;
        g_lp[b*2 + 1] += rb;
    }
}

// ---------------- f32x2 tiled SGEMM: C = act(Aconcat @ B^T + bias) -----------
// BM=128, BN=128, BK=16, 256 threads, 8x8 per thread (4 row-pairs x 8 cols).
__global__ void gemm2_kernel(const float* __restrict__ A1, int lda1,
                             const float* __restrict__ A2, int lda2, int split,
                             const float* __restrict__ Bm, int ldb,
                             const float* __restrict__ bias,
                             float* __restrict__ Cm, int ldc,
                             int Kdim, int doRelu) {
    __shared__ float As[16][130];
    __shared__ float Bs[16][132];
    int tid = threadIdx.x;
    int tx = tid & 15, ty = tid >> 4;
    int n0 = blockIdx.x * 128, m0 = blockIdx.y * 128;
    unsigned long long acc[4][8] = {};
    for (int k0 = 0; k0 < Kdim; k0 += 16) {
        for (int l = tid; l < 2048; l += 256) {
            int r = l >> 4, kk = l & 15;
            int kg = k0 + kk;
            float v = (kg < split) ? A1[(m0+r)*lda1 + kg]
                                   : A2[(m0+r)*lda2 + (kg - split)];
            As[kk][r] = v;
        }
        for (int l = tid; l < 2048; l += 256) {
            int n = l >> 4, kk = l & 15;
            Bs[kk][n] = Bm[(n0+n)*ldb + k0 + kk];
        }
        __syncthreads();
        #pragma unroll
        for (int kk = 0; kk < 16; kk++) {
            unsigned long long a2[4];
            #pragma unroll
            for (int i = 0; i < 4; i++)
                a2[i] = *(const unsigned long long*)&As[kk][ty*8 + 2*i];
            float4 b0 = *(const float4*)&Bs[kk][tx*8];
            float4 b1 = *(const float4*)&Bs[kk][tx*8 + 4];
            float bsv[8] = {b0.x,b0.y,b0.z,b0.w,b1.x,b1.y,b1.z,b1.w};
            #pragma unroll
            for (int j = 0; j < 8; j++) {
                unsigned long long bb; PACK2(bb, bsv[j]);
                #pragma unroll
                for (int i = 0; i < 4; i++) FMA2(acc[i][j], a2[i], bb);
            }
        }
        __syncthreads();
    }
    #pragma unroll
    for (int i = 0; i < 4; i++) {
        int mlo = m0 + ty*8 + 2*i;
        #pragma unroll
        for (int q = 0; q < 2; q++) {
            float lo[4], hi[4];
            #pragma unroll
            for (int j = 0; j < 4; j++) {
                int jj = q*4 + j;
                float bv = bias[n0 + tx*8 + jj];
                float vl = __uint_as_float((unsigned)acc[i][jj]) + bv;
                float vh = __uint_as_float((unsigned)(acc[i][jj] >> 32)) + bv;
                if (doRelu) { vl = fmaxf(vl, 0.f); vh = fmaxf(vh, 0.f); }
                lo[j] = vl; hi[j] = vh;
            }
            *(float4*)&Cm[mlo*ldc + n0 + tx*8 + q*4]     = make_float4(lo[0],lo[1],lo[2],lo[3]);
            *(float4*)&Cm[(mlo+1)*ldc + n0 + tx*8 + q*4] = make_float4(hi[0],hi[1],hi[2],hi[3]);
        }
    }
}

// ---------------- pool kernel: fused layer1 + layer2 GEMM (f32x2) + max ------
// Block tile: 4 i's x 24 j's = 96 rows, 128 output cols, K=512 in BK=32 tiles.
// Per thread: 3 row-pairs x 8 cols in f32x2.
__global__ void pool_kernel(const float* __restrict__ Wp2, const float* __restrict__ bp2) {
    int g  = blockIdx.z;
    int i0 = blockIdx.y * 4;
    int n0 = blockIdx.x * 128;
    __shared__ float As[32][104];
    __shared__ float Bs[32][132];
    __shared__ float hst[24][33];
    __shared__ float ra[96], rb[96];
    __shared__ int   red[4][128];
    int tid = threadIdx.x;
    int tx = tid & 15, ty = tid >> 4;

    if (tid < 96) {
        int il = tid / 24, j = tid % 24;
        float pix = g_lp[(g*24 + i0 + il)*2 + 0];
        float piy = g_lp[(g*24 + i0 + il)*2 + 1];
        float pjx = g_lp[(g*24 + j)*2 + 0];
        float pjy = g_lp[(g*24 + j)*2 + 1];
        float dx = pjx - pix, dy = pjy - piy;
        float nrm = sqrtf(dx*dx + dy*dy);
        float inv = 1.f / fmaxf(nrm, 1e-12f);
        ra[tid] = dx * inv;
        rb[tid] = dy * inv;
    }
    for (int l = tid; l < 512; l += 256) red[l >> 7][l & 127] = 0;
    __syncthreads();

    unsigned long long acc[3][8] = {};
    for (int k0 = 0; k0 < 512; k0 += 32) {
        // stage hcon tile 24x32 (coalesced, read once per block)
        for (int l = tid; l < 768; l += 256) {
            int jr = l >> 5, kk = l & 31;
            hst[jr][kk] = g_hcon[(g*24 + jr)*512 + k0 + kk];
        }
        // Bs tile 128x32 via float4 global loads
        for (int l = tid; l < 1024; l += 256) {
            int n = l >> 3, kc = (l & 7) * 4;
            const float4 w = *(const float4*)&Wp2[(n0 + n)*512 + k0 + kc];
            Bs[kc+0][n] = w.x; Bs[kc+1][n] = w.y; Bs[kc+2][n] = w.z; Bs[kc+3][n] = w.w;
        }
        __syncthreads();
        // A tile 96x32: fused layer-1 (r-major index -> conflict-free stores)
        for (int l = tid; l < 3072; l += 256) {
            int r = l % 96, kk = l / 96;
            int kg = k0 + kk;
            float v = ra[r]*g_M[kg*2] + rb[r]*g_M[kg*2 + 1] + hst[r % 24][kk];
            As[kk][r] = fmaxf(v, 0.f);
        }
        __syncthreads();
        #pragma unroll
        for (int kk = 0; kk < 32; kk++) {
            unsigned long long a2[3];
            #pragma unroll
            for (int i = 0; i < 3; i++)
                a2[i] = *(const unsigned long long*)&As[kk][ty*6 + 2*i];
            float4 b0 = *(const float4*)&Bs[kk][tx*8];
            float4 b1 = *(const float4*)&Bs[kk][tx*8 + 4];
            float bsv[8] = {b0.x,b0.y,b0.z,b0.w,b1.x,b1.y,b1.z,b1.w};
            #pragma unroll
            for (int j = 0; j < 8; j++) {
                unsigned long long bb; PACK2(bb, bsv[j]);
                FMA2(acc[0][j], a2[0], bb);
                FMA2(acc[1][j], a2[1], bb);
                FMA2(acc[2][j], a2[2], bb);
            }
        }
        __syncthreads();
    }
    // epilogue: relu(+bias) then max over 24 j-rows per i (int atomicMax ok: relu>=0)
    #pragma unroll
    for (int i = 0; i < 3; i++) {
        int r = ty*6 + 2*i;
        int il0 = r / 24, il1 = (r + 1) / 24;
        #pragma unroll
        for (int j = 0; j < 8; j++) {
            int n = tx*8 + j;
            float bv = bp2[n0 + n];
            float lo = fmaxf(__uint_as_float((unsigned)acc[i][j]) + bv, 0.f);
            float hi = fmaxf(__uint_as_float((unsigned)(acc[i][j] >> 32)) + bv, 0.f);
            atomicMax(&red[il0][n], __float_as_int(lo));
            atomicMax(&red[il1][n], __float_as_int(hi));
        }
    }
    __syncthreads();
    for (int l = tid; l < 512; l += 256) {
        int il = l >> 7, n = l & 127;
        g_pool[(g*24 + i0 + il)*1024 + n0 + n] = __int_as_float(red[il][n]);
    }
}

// ---------------- final hidden copy ------------------------------------------
__global__ void copyout_kernel(float* __restrict__ out) {
    int idx = blockIdx.x * blockDim.x + threadIdx.x;
    if (idx < BB*HD) out[SEQ*BB*2 + idx] = g_h[idx];
}

// ---------------- launch ------------------------------------------------------
static float* sym_addr(const void* sym) {
    void* p = nullptr;
    cudaGetSymbolAddress(&p, sym);
    return (float*)p;
}

extern "C" void kernel_launch(void* const* d_in, const int* in_sizes, int n_in,
                              void* d_out, int out_size) {
    const float* last_pos     = (const float*)d_in[0];
    const float* last_pos_rel = (const float*)d_in[1];
    const float* h0    = (const float*)d_in[2];
    const float* c0    = (const float*)d_in[3];
    const float* W_emb = (const float*)d_in[5];
    const float* b_emb = (const float*)d_in[6];
    const float* W_ih  = (const float*)d_in[7];
    const float* W_hh  = (const float*)d_in[8];
    const float* b_ih  = (const float*)d_in[9];
    const float* b_hh  = (const float*)d_in[10];
    const float* W_pos = (const float*)d_in[11];
    const float* b_pos = (const float*)d_in[12];
    const float* Wp_emb= (const float*)d_in[13];
    const float* bp_emb= (const float*)d_in[14];
    const float* Wp1   = (const float*)d_in[15];
    const float* bp1   = (const float*)d_in[16];
    const float* Wp2   = (const float*)d_in[17];
    const float* bp2   = (const float*)d_in[18];
    const float* Wm1   = (const float*)d_in[19];
    const float* bm1   = (const float*)d_in[20];
    const float* Wm2   = (const float*)d_in[21];
    const float* bm2   = (const float*)d_in[22];
    float* out = (float*)d_out;

    float* p_hl    = sym_addr(g_hl);
    float* p_h     = sym_addr(g_h);
    float* p_hcon  = sym_addr(g_hcon);
    float* p_pool  = sym_addr(g_pool);
    float* p_mh    = sym_addr(g_mh);
    float* p_biasc = sym_addr(g_biasc);

    precompute_kernel<<<(512*128 + 255)/256, 256>>>(W_ih, W_hh, Wp1, Wp_emb, bp_emb, bp1);
    init_kernel<<<(BB*HD + 255)/256, 256>>>(h0, c0, last_pos, last_pos_rel, W_emb, b_emb);

    for (int s = 0; s < SEQ; s++) {
        lstm_kernel<<<BB/8, 256>>>(b_ih, b_hh);
        posdec_kernel<<<BB, 128>>>(W_pos, b_pos, W_emb, b_emb, out, s);
        // hcon = hl @ Wp1_h^T + (bp1 + Wp1_e@bp_emb):  [1536,512], K=128
        gemm2_kernel<<<dim3(512/128, BB/128), 256>>>(
            p_hl, 128, p_hl, 128, 1 << 28,
            Wp1 + 64, 192, p_biasc, p_hcon, 512, 128, 0);
        // pool: fused layer1 + [36864,512]@[512,1024]^T + max over j
        pool_kernel<<<dim3(8, 6, NG), 256>>>(Wp2, bp2);
        // mlp1: concat(hl, pool) [1536,1152] @ Wm1^T -> [1536,1024], relu
        gemm2_kernel<<<dim3(1024/128, BB/128), 256>>>(
            p_hl, 128, p_pool, 1024, 128,
            Wm1, 1152, bm1, p_mh, 1024, 1152, 1);
        // mlp2: [1536,1024] @ Wm2^T -> [1536,128], relu -> refreshed h (carry)
        gemm2_kernel<<<dim3(128/128, BB/128), 256>>>(
            p_mh, 1024, p_mh, 1024, 1 << 28,
            Wm2, 1024, bm2, p_h, 128, 1024, 1);
    }
    copyout_kernel<<<(BB*HD + 255)/256, 256>>>(out);
}

// round 3
// speedup vs baseline: 1.0976x; 1.0976x over previous
#include <cuda_runtime.h>
#include <math.h>

#define BB 1536
#define NG 64
#define NP 24
#define ED 64
#define HD 128
#define SEQ 12

// ---------------- scratch (static device globals; no allocation) -------------
__device__ float g_h[BB*HD];        // carry hidden (refreshed by mlp2)
__device__ float g_c[BB*HD];        // LSTM cell
__device__ float g_hl[BB*HD];       // LSTM output h for this step
__device__ float g_lp[BB*2];        // current position
__device__ float g_decin[BB*ED];    // decoder input embedding
__device__ float g_hcon[BB*512];    // h @ Wp1_h^T + combined bias (pre-relu)
__device__ float g_pool[BB*1024];   // pooled features
__device__ float g_mh[BB*1024];     // mlp hidden
__device__ float g_M0[512];         // Wp1_e @ Wp_emb col 0
__device__ float g_M1[512];         // Wp1_e @ Wp_emb col 1
__device__ float g_biasc[512];      // bp1 + Wp1_e @ bp_emb
__device__ float g_WihT[64*512];    // transposed LSTM weights
__device__ float g_WhhT[128*512];

// ---------------- tf32 helpers ------------------------------------------------
__device__ __forceinline__ float2 split_tf32(float v) {
    unsigned hu; asm("cvt.rna.tf32.f32 %0, %1;" : "=r"(hu) : "f"(v));
    float hi = __uint_as_float(hu);
    float rem = v - hi;                                 // exact (Dekker)
    unsigned lu; asm("cvt.rna.tf32.f32 %0, %1;" : "=r"(lu) : "f"(rem));
    return make_float2(hi, __uint_as_float(lu));
}

__device__ __forceinline__ void mma8(float* c, float a0, float a1, float a2, float a3,
                                     float b0, float b1) {
    asm("mma.sync.aligned.m16n8k8.row.col.f32.tf32.tf32.f32 "
        "{%0,%1,%2,%3},{%4,%5,%6,%7},{%8,%9},{%0,%1,%2,%3};"
        : "+f"(c[0]), "+f"(c[1]), "+f"(c[2]), "+f"(c[3])
        : "r"(__float_as_uint(a0)), "r"(__float_as_uint(a1)),
          "r"(__float_as_uint(a2)), "r"(__float_as_uint(a3)),
          "r"(__float_as_uint(b0)), "r"(__float_as_uint(b1)));
}

// 3xTF32: D += Ahi*Bhi + Ahi*Blo + Alo*Bhi   (a*,b* are (hi,lo) float2 frags)
__device__ __forceinline__ void mma3(float* c, const float2* a, const float2* b) {
    mma8(c, a[0].x, a[1].x, a[2].x, a[3].x, b[0].x, b[1].x);
    mma8(c, a[0].x, a[1].x, a[2].x, a[3].x, b[0].y, b[1].y);
    mma8(c, a[0].y, a[1].y, a[2].y, a[3].y, b[0].x, b[1].x);
}

// ---------------- precompute --------------------------------------------------
__global__ void precompute_kernel(const float* __restrict__ Wih,
                                  const float* __restrict__ Whh,
                                  const float* __restrict__ Wp1,
                                  const float* __restrict__ Wp_emb,
                                  const float* __restrict__ bp_emb,
                                  const float* __restrict__ bp1) {
    int idx = blockIdx.x * blockDim.x + threadIdx.x;
    if (idx < 512*64)  { int r = idx/64,  c = idx%64;  g_WihT[c*512 + r] = Wih[idx]; }
    if (idx < 512*128) { int r = idx/128, c = idx%128; g_WhhT[c*512 + r] = Whh[idx]; }
    if (idx < 512) {
        float m0 = 0.f, m1 = 0.f, bc = 0.f;
        for (int e = 0; e < 64; e++) {
            float w = Wp1[idx*192 + e];
            m0 += w * Wp_emb[e*2 + 0];
            m1 += w * Wp_emb[e*2 + 1];
            bc += w * bp_emb[e];
        }
        g_M0[idx] = m0;
        g_M1[idx] = m1;
        g_biasc[idx] = bp1[idx] + bc;
    }
}

// ---------------- init --------------------------------------------------------
__global__ void init_kernel(const float* __restrict__ h0, const float* __restrict__ c0,
                            const float* __restrict__ lp, const float* __restrict__ lpr,
                            const float* __restrict__ Wemb, const float* __restrict__ bemb) {
    int idx = blockIdx.x * blockDim.x + threadIdx.x;
    if (idx < BB*HD) { g_h[idx] = h0[idx]; g_c[idx] = c0[idx]; }
    if (idx < BB*2)  { g_lp[idx] = lp[idx]; }
    if (idx < BB*ED) {
        int b = idx / ED, e = idx % ED;
        g_decin[idx] = lpr[b*2]*Wemb[e*2] + lpr[b*2+1]*Wemb[e*2+1] + bemb[e];
    }
}

// ---------------- fused LSTM step ---------------------------------------------
__global__ void lstm_kernel(const float* __restrict__ bih, const float* __restrict__ bhh) {
    int tid = threadIdx.x;
    int u = tid & 127;
    int rh = tid >> 7;
    int r0 = blockIdx.x * 8;
    __shared__ float xs[8][64];
    __shared__ float hs[8][128];
    for (int l = tid; l < 8*64;  l += 256) xs[l>>6][l&63]  = g_decin[r0*64  + l];
    for (int l = tid; l < 8*128; l += 256) hs[l>>7][l&127] = g_h[r0*128 + l];
    __syncthreads();

    float acc[4][4];
    #pragma unroll
    for (int gt = 0; gt < 4; gt++) {
        float bb = bih[u + gt*128] + bhh[u + gt*128];
        #pragma unroll
        for (int r = 0; r < 4; r++) acc[gt][r] = bb;
    }
    for (int e = 0; e < 64; e++) {
        float w0 = g_WihT[e*512 + u];
        float w1 = g_WihT[e*512 + u + 128];
        float w2 = g_WihT[e*512 + u + 256];
        float w3 = g_WihT[e*512 + u + 384];
        #pragma unroll
        for (int r = 0; r < 4; r++) {
            float x = xs[rh*4 + r][e];
            acc[0][r] += w0*x; acc[1][r] += w1*x; acc[2][r] += w2*x; acc[3][r] += w3*x;
        }
    }
    for (int e = 0; e < 128; e++) {
        float w0 = g_WhhT[e*512 + u];
        float w1 = g_WhhT[e*512 + u + 128];
        float w2 = g_WhhT[e*512 + u + 256];
        float w3 = g_WhhT[e*512 + u + 384];
        #pragma unroll
        for (int r = 0; r < 4; r++) {
            float x = hs[rh*4 + r][e];
            acc[0][r] += w0*x; acc[1][r] += w1*x; acc[2][r] += w2*x; acc[3][r] += w3*x;
        }
    }
    #pragma unroll
    for (int r = 0; r < 4; r++) {
        int row = r0 + rh*4 + r;
        float ig = 1.f / (1.f + __expf(-acc[0][r]));
        float fg = 1.f / (1.f + __expf(-acc[1][r]));
        float gg = tanhf(acc[2][r]);
        float og = 1.f / (1.f + __expf(-acc[3][r]));
        int bi = row*128 + u;
        float cc = fg * g_c[bi] + ig * gg;
        g_c[bi]  = cc;
        g_hl[bi] = og * tanhf(cc);
    }
}

// ---------------- rel_pos, position update, rels output, next dec_in ---------
__global__ void posdec_kernel(const float* __restrict__ Wpos, const float* __restrict__ bpos,
                              const float* __restrict__ Wemb, const float* __restrict__ bemb,
                              float* __restrict__ rels_out, int step) {
    int b = blockIdx.x;
    int t = threadIdx.x;
    __shared__ float hr[128];
    __shared__ float sr[2];
    hr[t] = g_hl[b*128 + t];
    __syncthreads();
    int w = t >> 5, lane = t & 31;
    if (w < 2) {
        float part = 0.f;
        for (int k = lane; k < 128; k += 32) part += hr[k] * Wpos[w*128 + k];
        #pragma unroll
        for (int off = 16; off; off >>= 1) part += __shfl_down_sync(0xffffffffu, part, off);
        if (lane == 0) sr[w] = part + bpos[w];
    }
    __syncthreads();
    float ra = sr[0], rb = sr[1];
    if (t < 64) g_decin[b*64 + t] = ra*Wemb[t*2] + rb*Wemb[t*2+1] + bemb[t];
    if (t == 0) {
        rels_out[(step*BB + b)*2 + 0] = ra;
        rels_out[(step*BB + b)*2 + 1] = rb;
        g_lp[b*2 + 0] += ra;
        g_lp[b*2 + 1] += rb;
    }
}

// ---------------- generic 3xTF32 MMA GEMM: C = act(Aconcat @ B^T + bias) -----
// 96x128 block, 8 warps (2x4), warp tile 48x32 (3x4 m16n8k8 tiles), BK=16.
__global__ void gemm_mma_kernel(const float* __restrict__ A1, int lda1,
                                const float* __restrict__ A2, int lda2, int split,
                                const float* __restrict__ Bm, int ldb,
                                const float* __restrict__ bias,
                                float* __restrict__ Cm, int ldc,
                                int Kdim, int doRelu) {
    __shared__ __align__(16) float As2[16][200];  // (hi,lo) pairs, m*2+s, stride 200
    __shared__ __align__(16) float Bs2[16][264];  // (hi,lo) pairs, n*2+s, stride 264
    int tid = threadIdx.x;
    int lane = tid & 31, wid = tid >> 5;
    int g = lane >> 2, tg = lane & 3;
    int warpM = wid >> 2, warpN = wid & 3;
    int n0 = blockIdx.x * 128, m0 = blockIdx.y * 96;

    float acc[3][4][4];
    #pragma unroll
    for (int mt = 0; mt < 3; mt++)
        #pragma unroll
        for (int nt = 0; nt < 4; nt++)
            #pragma unroll
            for (int q = 0; q < 4; q++) acc[mt][nt][q] = 0.f;

    for (int k0 = 0; k0 < Kdim; k0 += 16) {
        // A tile 96x16 -> (hi,lo)
        for (int e = tid; e < 1536; e += 256) {
            int r = e >> 4, kk = e & 15;
            int kg = k0 + kk;
            float v = (kg < split) ? A1[(m0+r)*lda1 + kg]
                                   : A2[(m0+r)*lda2 + (kg - split)];
            ((float2*)&As2[kk][0])[r] = split_tf32(v);
        }
        // B tile 128x16 -> (hi,lo)
        {
            int n = tid >> 1;
            int kcb = (tid & 1) * 8;
            #pragma unroll
            for (int it = 0; it < 2; it++) {
                int kc = kcb + it*4;
                const float4 w = *(const float4*)&Bm[(n0+n)*ldb + k0 + kc];
                ((float2*)&Bs2[kc+0][0])[n] = split_tf32(w.x);
                ((float2*)&Bs2[kc+1][0])[n] = split_tf32(w.y);
                ((float2*)&Bs2[kc+2][0])[n] = split_tf32(w.z);
                ((float2*)&Bs2[kc+3][0])[n] = split_tf32(w.w);
            }
        }
        __syncthreads();
        #pragma unroll
        for (int ks = 0; ks < 2; ks++) {
            int kb = ks * 8;
            float2 aF[3][4];
            #pragma unroll
            for (int mt = 0; mt < 3; mt++) {
                int rb = warpM*48 + mt*16;
                const float2* Ak0 = (const float2*)&As2[kb+tg][0];
                const float2* Ak4 = (const float2*)&As2[kb+tg+4][0];
                aF[mt][0] = Ak0[rb + g];
                aF[mt][1] = Ak0[rb + g + 8];
                aF[mt][2] = Ak4[rb + g];
                aF[mt][3] = Ak4[rb + g + 8];
            }
            float2 bF[4][2];
            #pragma unroll
            for (int nt = 0; nt < 4; nt++) {
                int nb = warpN*32 + nt*8;
                bF[nt][0] = ((const float2*)&Bs2[kb+tg][0])[nb + g];
                bF[nt][1] = ((const float2*)&Bs2[kb+tg+4][0])[nb + g];
            }
            #pragma unroll
            for (int mt = 0; mt < 3; mt++)
                #pragma unroll
                for (int nt = 0; nt < 4; nt++)
                    mma3(acc[mt][nt], aF[mt], bF[nt]);
        }
        __syncthreads();
    }
    // epilogue
    #pragma unroll
    for (int mt = 0; mt < 3; mt++) {
        int r0 = m0 + warpM*48 + mt*16 + g;
        #pragma unroll
        for (int nt = 0; nt < 4; nt++) {
            int c0 = n0 + warpN*32 + nt*8 + 2*tg;
            float b0v = bias[c0], b1v = bias[c0+1];
            float v0 = acc[mt][nt][0] + b0v;
            float v1 = acc[mt][nt][1] + b1v;
            float v2 = acc[mt][nt][2] + b0v;
            float v3 = acc[mt][nt][3] + b1v;
            if (doRelu) {
                v0 = fmaxf(v0, 0.f); v1 = fmaxf(v1, 0.f);
                v2 = fmaxf(v2, 0.f); v3 = fmaxf(v3, 0.f);
            }
            *(float2*)&Cm[r0*ldc + c0]     = make_float2(v0, v1);
            *(float2*)&Cm[(r0+8)*ldc + c0] = make_float2(v2, v3);
        }
    }
}

// ---------------- pool kernel: fused layer1 + 3xTF32 MMA layer2 + max over j -
// Block: 4 i's x 24 j's = 96 rows, 128 cols, K=512, BK=16.
__global__ void pool_mma_kernel(const float* __restrict__ Wp2, const float* __restrict__ bp2) {
    __shared__ __align__(16) float As2[16][200];
    __shared__ __align__(16) float Bs2[16][264];
    __shared__ float ra[96], rb[96];
    __shared__ int   red[4][128];
    int grp = blockIdx.z;
    int i0  = blockIdx.y * 4;
    int n0  = blockIdx.x * 128;
    int tid = threadIdx.x;
    int lane = tid & 31, wid = tid >> 5;
    int g = lane >> 2, tg = lane & 3;
    int warpM = wid >> 2, warpN = wid & 3;

    if (tid < 96) {
        int il = tid / 24, j = tid % 24;
        float pix = g_lp[(grp*24 + i0 + il)*2 + 0];
        float piy = g_lp[(grp*24 + i0 + il)*2 + 1];
        float pjx = g_lp[(grp*24 + j)*2 + 0];
        float pjy = g_lp[(grp*24 + j)*2 + 1];
        float dx = pjx - pix, dy = pjy - piy;
        float nrm = sqrtf(dx*dx + dy*dy);
        float inv = 1.f / fmaxf(nrm, 1e-12f);
        ra[tid] = dx * inv;
        rb[tid] = dy * inv;
    }
    for (int l = tid; l < 512; l += 256) red[l >> 7][l & 127] = 0;
    __syncthreads();

    float acc[3][4][4];
    #pragma unroll
    for (int mt = 0; mt < 3; mt++)
        #pragma unroll
        for (int nt = 0; nt < 4; nt++)
            #pragma unroll
            for (int q = 0; q < 4; q++) acc[mt][nt][q] = 0.f;

    for (int k0 = 0; k0 < 512; k0 += 16) {
        // A tile 96x16: fused pool layer-1, relu, tf32 split
        for (int e = tid; e < 1536; e += 256) {
            int r = e >> 4, kk = e & 15;
            int kg = k0 + kk;
            float hc = g_hcon[(grp*24 + (r % 24))*512 + kg];
            float v = fmaxf(fmaf(ra[r], g_M0[kg], fmaf(rb[r], g_M1[kg], hc)), 0.f);
            ((float2*)&As2[kk][0])[r] = split_tf32(v);
        }
        // B tile 128x16 of Wp2
        {
            int n = tid >> 1;
            int kcb = (tid & 1) * 8;
            #pragma unroll
            for (int it = 0; it < 2; it++) {
                int kc = kcb + it*4;
                const float4 w = *(const float4*)&Wp2[(n0+n)*512 + k0 + kc];
                ((float2*)&Bs2[kc+0][0])[n] = split_tf32(w.x);
                ((float2*)&Bs2[kc+1][0])[n] = split_tf32(w.y);
                ((float2*)&Bs2[kc+2][0])[n] = split_tf32(w.z);
                ((float2*)&Bs2[kc+3][0])[n] = split_tf32(w.w);
            }
        }
        __syncthreads();
        #pragma unroll
        for (int ks = 0; ks < 2; ks++) {
            int kb = ks * 8;
            float2 aF[3][4];
            #pragma unroll
            for (int mt = 0; mt < 3; mt++) {
                int rb2 = warpM*48 + mt*16;
                const float2* Ak0 = (const float2*)&As2[kb+tg][0];
                const float2* Ak4 = (const float2*)&As2[kb+tg+4][0];
                aF[mt][0] = Ak0[rb2 + g];
                aF[mt][1] = Ak0[rb2 + g + 8];
                aF[mt][2] = Ak4[rb2 + g];
                aF[mt][3] = Ak4[rb2 + g + 8];
            }
            float2 bF[4][2];
            #pragma unroll
            for (int nt = 0; nt < 4; nt++) {
                int nb = warpN*32 + nt*8;
                bF[nt][0] = ((const float2*)&Bs2[kb+tg][0])[nb + g];
                bF[nt][1] = ((const float2*)&Bs2[kb+tg+4][0])[nb + g];
            }
            #pragma unroll
            for (int mt = 0; mt < 3; mt++)
                #pragma unroll
                for (int nt = 0; nt < 4; nt++)
                    mma3(acc[mt][nt], aF[mt], bF[nt]);
        }
        __syncthreads();
    }
    // epilogue: +bias, relu, max over the 24 j-rows of each i (relu>=0 -> int max ok)
    #pragma unroll
    for (int mt = 0; mt < 3; mt++) {
        int r = warpM*48 + mt*16 + g;
        int il0 = r / 24, il8 = (r + 8) / 24;
        #pragma unroll
        for (int nt = 0; nt < 4; nt++) {
            int n = warpN*32 + nt*8 + 2*tg;
            float b0v = bp2[n0 + n], b1v = bp2[n0 + n + 1];
            atomicMax(&red[il0][n],     __float_as_int(fmaxf(acc[mt][nt][0] + b0v, 0.f)));
            atomicMax(&red[il0][n + 1], __float_as_int(fmaxf(acc[mt][nt][1] + b1v, 0.f)));
            atomicMax(&red[il8][n],     __float_as_int(fmaxf(acc[mt][nt][2] + b0v, 0.f)));
            atomicMax(&red[il8][n + 1], __float_as_int(fmaxf(acc[mt][nt][3] + b1v, 0.f)));
        }
    }
    __syncthreads();
    for (int l = tid; l < 512; l += 256) {
        int il = l >> 7, n = l & 127;
        g_pool[(grp*24 + i0 + il)*1024 + n0 + n] = __int_as_float(red[il][n]);
    }
}

// ---------------- final hidden copy ------------------------------------------
__global__ void copyout_kernel(float* __restrict__ out) {
    int idx = blockIdx.x * blockDim.x + threadIdx.x;
    if (idx < BB*HD) out[SEQ*BB*2 + idx] = g_h[idx];
}

// ---------------- launch ------------------------------------------------------
static float* sym_addr(const void* sym) {
    void* p = nullptr;
    cudaGetSymbolAddress(&p, sym);
    return (float*)p;
}

extern "C" void kernel_launch(void* const* d_in, const int* in_sizes, int n_in,
                              void* d_out, int out_size) {
    const float* last_pos     = (const float*)d_in[0];
    const float* last_pos_rel = (const float*)d_in[1];
    const float* h0    = (const float*)d_in[2];
    const float* c0    = (const float*)d_in[3];
    const float* W_emb = (const float*)d_in[5];
    const float* b_emb = (const float*)d_in[6];
    const float* W_ih  = (const float*)d_in[7];
    const float* W_hh  = (const float*)d_in[8];
    const float* b_ih  = (const float*)d_in[9];
    const float* b_hh  = (const float*)d_in[10];
    const float* W_pos = (const float*)d_in[11];
    const float* b_pos = (const float*)d_in[12];
    const float* Wp_emb= (const float*)d_in[13];
    const float* bp_emb= (const float*)d_in[14];
    const float* Wp1   = (const float*)d_in[15];
    const float* bp1   = (const float*)d_in[16];
    const float* Wp2   = (const float*)d_in[17];
    const float* bp2   = (const float*)d_in[18];
    const float* Wm1   = (const float*)d_in[19];
    const float* bm1   = (const float*)d_in[20];
    const float* Wm2   = (const float*)d_in[21];
    const float* bm2   = (const float*)d_in[22];
    float* out = (float*)d_out;

    float* p_hl    = sym_addr(g_hl);
    float* p_h     = sym_addr(g_h);
    float* p_hcon  = sym_addr(g_hcon);
    float* p_pool  = sym_addr(g_pool);
    float* p_mh    = sym_addr(g_mh);
    float* p_biasc = sym_addr(g_biasc);

    precompute_kernel<<<(512*128 + 255)/256, 256>>>(W_ih, W_hh, Wp1, Wp_emb, bp_emb, bp1);
    init_kernel<<<(BB*HD + 255)/256, 256>>>(h0, c0, last_pos, last_pos_rel, W_emb, b_emb);

    for (int s = 0; s < SEQ; s++) {
        lstm_kernel<<<BB/8, 256>>>(b_ih, b_hh);
        posdec_kernel<<<BB, 128>>>(W_pos, b_pos, W_emb, b_emb, out, s);
        // hcon = hl @ Wp1_h^T + (bp1 + Wp1_e@bp_emb):  [1536,512], K=128
        gemm_mma_kernel<<<dim3(512/128, BB/96), 256>>>(
            p_hl, 128, p_hl, 128, 1 << 28,
            Wp1 + 64, 192, p_biasc, p_hcon, 512, 128, 0);
        // pool: fused layer1 + [36864,512]@[512,1024]^T + max over j
        pool_mma_kernel<<<dim3(8, 6, NG), 256>>>(Wp2, bp2);
        // mlp1: concat(hl, pool) [1536,1152] @ Wm1^T -> [1536,1024], relu
        gemm_mma_kernel<<<dim3(1024/128, BB/96), 256>>>(
            p_hl, 128, p_pool, 1024, 128,
            Wm1, 1152, bm1, p_mh, 1024, 1152, 1);
        // mlp2: [1536,1024] @ Wm2^T -> [1536,128], relu -> refreshed h (carry)
        gemm_mma_kernel<<<dim3(128/128, BB/96), 256>>>(
            p_mh, 1024, p_mh, 1024, 1 << 28,
            Wm2, 1024, bm2, p_h, 128, 1024, 1);
    }
    copyout_kernel<<<(BB*HD + 255)/256, 256>>>(out);
}